// round 7
// baseline (speedup 1.0000x reference)
#include <cuda_runtime.h>
#include <math.h>

#define MAX_NODES 50000
#define MAX_EDGES 600000
#define DIM 128              // 32 float4 per row
#define SCAN_TILE 1024
#define MAX_TILES ((MAX_NODES + SCAN_TILE - 1) / SCAN_TILE)   // 49

// ---- scratch (no dynamic allocation; __device__ globals are zero-init) ----
__device__ int                g_counts[MAX_NODES];   // invariant: zero at call entry
__device__ int                g_offs[MAX_NODES + 1];
__device__ int                g_cursor[MAX_NODES];
__device__ unsigned long long g_csr_se[MAX_EDGES];   // packed src|dst<<16|eid<<32, CSR order
__device__ float              g_ex[MAX_EDGES];       // exp(logit), CSR order

// ---------------------------------------------------------------------------
__global__ void k_hist(const int* __restrict__ dst, int E) {
    int i = blockIdx.x * blockDim.x + threadIdx.x;
    if (i < E) atomicAdd(&g_counts[dst[i]], 1);
}

// Fused scan: block b computes base = sum(counts[0 : b*1024)) directly
// (L2-resident, <=48 coalesced reads per thread), then scans its own tile.
// Nobody writes g_counts here (re-zeroed later in k_node_agg) -> race-free.
__global__ void k_scan(int n, int E) {
    __shared__ int s[SCAN_TILE];
    __shared__ int sred[32];

    // 1) sum of all preceding tiles
    int before = blockIdx.x * SCAN_TILE;
    int partial = 0;
    for (int i = threadIdx.x; i < before; i += SCAN_TILE) partial += g_counts[i];
    #pragma unroll
    for (int o = 16; o; o >>= 1) partial += __shfl_xor_sync(0xFFFFFFFFu, partial, o);
    if ((threadIdx.x & 31) == 0) sred[threadIdx.x >> 5] = partial;
    __syncthreads();
    int base;
    {
        int v = sred[threadIdx.x & 31];
        #pragma unroll
        for (int o = 16; o; o >>= 1) v += __shfl_xor_sync(0xFFFFFFFFu, v, o);
        base = v;
    }

    // 2) tile-local inclusive scan (Hillis-Steele)
    int i = before + threadIdx.x;
    int v = (i < n) ? g_counts[i] : 0;
    s[threadIdx.x] = v;
    __syncthreads();
    #pragma unroll
    for (int off = 1; off < SCAN_TILE; off <<= 1) {
        int t = (threadIdx.x >= off) ? s[threadIdx.x - off] : 0;
        __syncthreads();
        s[threadIdx.x] += t;
        __syncthreads();
    }
    if (i < n) {
        int off = base + s[threadIdx.x] - v;   // exclusive
        g_offs[i]   = off;
        g_cursor[i] = off;
    }
    if (blockIdx.x == 0 && threadIdx.x == 0) g_offs[n] = E;
}

// Scatter: ONE random 8-byte store per edge (packed payload).
__global__ void k_scatter(const int* __restrict__ src, const int* __restrict__ dst, int E) {
    int i = blockIdx.x * blockDim.x + threadIdx.x;
    if (i < E) {
        int d = dst[i];
        int pos = atomicAdd(&g_cursor[d], 1);
        g_csr_se[pos] = (unsigned long long)(unsigned)src[i]
                      | ((unsigned long long)(unsigned)d << 16)
                      | ((unsigned long long)(unsigned)i << 32);
    }
}

// ---------------------------------------------------------------------------
// K4: per-CSR-slot logits (warp per slot; lane handles one float4 = 4 dims).
// Stores exp(logit) directly (|logit| <~ 6, exp safe in fp32; softmax is
// shift-invariant so skipping max-subtraction is mathematically identical).
__global__ void __launch_bounds__(512)
k_edge_logits(const float4* __restrict__ hv,
              const float4* __restrict__ hd,
              const float4* __restrict__ Wpi,
              const float4* __restrict__ WM,
              int E) {
    int slot = (blockIdx.x * blockDim.x + threadIdx.x) >> 5;
    int lane = threadIdx.x & 31;
    if (slot >= E) return;
    unsigned long long p = __ldg(&g_csr_se[slot]);
    int s  = (int)(p & 0xFFFFu);
    int dn = (int)((p >> 16) & 0xFFFFu);
    int e  = (int)(p >> 32);

    float4 fs = hv[s * 32 + lane];
    float4 fd = hv[dn * 32 + lane];                   // shared across consecutive slots
    float4 h  = __ldcs(&hd[(size_t)e * 32 + lane]);   // streamed once: evict-first
    float4 wp = __ldg(&Wpi[lane]);
    float4 w1 = __ldg(&WM[lane]);
    float4 w2 = __ldg(&WM[32 + lane]);

    float px = fs.x * fd.x, py = fs.y * fd.y, pz = fs.z * fd.z, pw = fs.w * fd.w;
    float ep = px * h.x * wp.x + py * h.y * wp.y + pz * h.z * wp.z + pw * h.w * wp.w;
    float mp = px * w1.x + py * w1.y + pz * w1.z + pw * w1.w
             + h.x * w2.x + h.y * w2.y + h.z * w2.z + h.w * w2.w;

    #pragma unroll
    for (int o = 16; o; o >>= 1) {
        ep += __shfl_xor_sync(0xFFFFFFFFu, ep, o);
        mp += __shfl_xor_sync(0xFFFFFFFFu, mp, o);
    }
    if (lane == 0) {
        float mask = 1.0f / (1.0f + expf(-mp));
        g_ex[slot] = expf(ep * mask);                 // sequential store
    }
}

// ---------------------------------------------------------------------------
// K5: warp per destination node: normalize + weighted sum of h_v[src].
// Two passes only (sum of exp; aggregate). Also re-zeroes g_counts.
__global__ void __launch_bounds__(256)
k_node_agg(const float4* __restrict__ hv,
           float4* __restrict__ out,
           int N) {
    int warp = (blockIdx.x * blockDim.x + threadIdx.x) >> 5;
    int lane = threadIdx.x & 31;
    if (warp >= N) return;
    int beg = g_offs[warp], end = g_offs[warp + 1];
    if (lane == 0) g_counts[warp] = 0;     // restore scratch invariant

    // pass 1: sum of exp
    float se = 0.0f;
    for (int j = beg + lane; j < end; j += 32) se += g_ex[j];
    #pragma unroll
    for (int o = 16; o; o >>= 1) se += __shfl_xor_sync(0xFFFFFFFFu, se, o);
    float inv = (se > 0.0f) ? 1.0f / se : 0.0f;

    // pass 2: weighted feature aggregation, 2x unrolled for load MLP
    float4 acc = make_float4(0.f, 0.f, 0.f, 0.f);
    int j = beg;
    for (; j + 1 < end; j += 2) {
        float a0 = g_ex[j]     * inv;
        float a1 = g_ex[j + 1] * inv;
        int s0 = (int)(g_csr_se[j]     & 0xFFFFu);
        int s1 = (int)(g_csr_se[j + 1] & 0xFFFFu);
        float4 v0 = hv[s0 * 32 + lane];
        float4 v1 = hv[s1 * 32 + lane];
        acc.x += a0 * v0.x + a1 * v1.x;
        acc.y += a0 * v0.y + a1 * v1.y;
        acc.z += a0 * v0.z + a1 * v1.z;
        acc.w += a0 * v0.w + a1 * v1.w;
    }
    if (j < end) {
        float a = g_ex[j] * inv;
        int s = (int)(g_csr_se[j] & 0xFFFFu);
        float4 v = hv[s * 32 + lane];
        acc.x += a * v.x; acc.y += a * v.y; acc.z += a * v.z; acc.w += a * v.w;
    }
    out[warp * 32 + lane] = acc;
}

// ---------------------------------------------------------------------------
extern "C" void kernel_launch(void* const* d_in, const int* in_sizes, int n_in,
                              void* d_out, int out_size) {
    const float4* hv  = (const float4*)d_in[0];
    const float4* hd  = (const float4*)d_in[1];
    const float4* Wpi = (const float4*)d_in[2];
    const float4* WM  = (const float4*)d_in[3];
    const int*    src = (const int*)d_in[4];
    const int*    dst = (const int*)d_in[5];

    int N = in_sizes[0] / DIM;
    int E = in_sizes[4];
    int tiles = (N + SCAN_TILE - 1) / SCAN_TILE;

    // CSR build: 3 launches (counts zero at entry; node_agg re-zeroes them)
    k_hist   <<<(E + 255) / 256, 256>>>(dst, E);
    k_scan   <<<tiles, SCAN_TILE>>>(N, E);
    k_scatter<<<(E + 255) / 256, 256>>>(src, dst, E);

    // per-slot logits in CSR order: warp per slot, 16 warps/block
    k_edge_logits<<<(E + 15) / 16, 512>>>(hv, hd, Wpi, WM, E);

    // per-node normalize + aggregation: warp per node
    k_node_agg<<<(N + 7) / 8, 256>>>(hv, (float4*)d_out, N);
}